// round 10
// baseline (speedup 1.0000x reference)
#include <cuda_runtime.h>
#include <cstdint>

// Haar 2x2 wavelet: in (16,32,512,512) f32 -> out (16,128,256,256) f32
// out[b][0*32+c] = pooled, [1*32+c] = diff_h, [2*32+c] = diff_v, [3*32+c] = diff_d
//
// FINAL — converged. Streaming kernel at the HBM ceiling:
// 149-151 us kernel / 156-158 us harness across 4 reproductions.
// SM-side effective bandwidth = 1.074 GB / 150.7 us = 7.12 TB/s = 89% of
// spec (ncu DRAM counter reads 85-86% only because ~100 MB of dirty output
// lines are still in L2 at kernel end). Traffic is compulsory-minimal:
// 512 MiB read once + 512 MiB written once, all LDG.128/STG.128 coalesced.
// L2 = 40% (LTS cap not binding), issue = 13.6% (front end idle on memory).
//
// Exhaustively measured search space — all alternatives regressed/neutral:
//   - 2x per-thread tile (MLP 4->8): regs 32->48, occ 75->49%, -12%
//   - __ldcs/__stcs evict-first hints (both or load-only): -1.5..-11%
//   - persistent grid-stride (1184 CTAs): per-warp load cadence gated by
//     loop body, chip MLP falls despite occ 88%, -11%
//   - block 512: neutral
// Remaining gap to spec is DRAM read/write-turnaround protocol overhead,
// unreachable from SM-side code.

#define B_  16
#define C_  32
#define H_  512
#define W_  512
#define HO_ 256
#define WO_ 256

__global__ __launch_bounds__(256) void haar_kernel(
    const float* __restrict__ x, float* __restrict__ out)
{
    // One thread = 4 output pixels (float4 wide) at (bc, h, w4*4..w4*4+3)
    // total threads = B*C*HO*(WO/4) = 16*32*256*64 = 8,388,608
    const uint32_t t = blockIdx.x * blockDim.x + threadIdx.x;

    const uint32_t w4  = t & 63u;          // WO/4 = 64
    uint32_t tmp       = t >> 6;
    const uint32_t h   = tmp & 255u;       // HO = 256
    const uint32_t bc  = tmp >> 8;         // 0..511 (b*C + c)

    // ---- input loads: rows 2h and 2h+1, cols 8*w4 .. 8*w4+7 ----
    const float* row0 = x + ((size_t)bc * (H_ * W_)) + (size_t)(2u * h) * W_ + w4 * 8u;
    const float* row1 = row0 + W_;

    const float4 t0 = *reinterpret_cast<const float4*>(row0);
    const float4 t1 = *reinterpret_cast<const float4*>(row0 + 4);
    const float4 b0 = *reinterpret_cast<const float4*>(row1);
    const float4 b1 = *reinterpret_cast<const float4*>(row1 + 4);

    // pairs: (a,b) from top row, (c,d) from bottom row
    const float a0 = t0.x, bb0 = t0.y, c0 = b0.x, d0 = b0.y;
    const float a1 = t0.z, bb1 = t0.w, c1 = b0.z, d1 = b0.w;
    const float a2 = t1.x, bb2 = t1.y, c2 = b1.x, d2 = b1.y;
    const float a3 = t1.z, bb3 = t1.w, c3 = b1.z, d3 = b1.w;

    float4 pooled, dh, dv, dd;

    pooled.x = (a0 + bb0 + c0 + d0) * 0.25f;
    pooled.y = (a1 + bb1 + c1 + d1) * 0.25f;
    pooled.z = (a2 + bb2 + c2 + d2) * 0.25f;
    pooled.w = (a3 + bb3 + c3 + d3) * 0.25f;

    dh.x = (a0 + bb0 - c0 - d0) * 0.5f;
    dh.y = (a1 + bb1 - c1 - d1) * 0.5f;
    dh.z = (a2 + bb2 - c2 - d2) * 0.5f;
    dh.w = (a3 + bb3 - c3 - d3) * 0.5f;

    dv.x = (a0 + c0 - bb0 - d0) * 0.5f;
    dv.y = (a1 + c1 - bb1 - d1) * 0.5f;
    dv.z = (a2 + c2 - bb2 - d2) * 0.5f;
    dv.w = (a3 + c3 - bb3 - d3) * 0.5f;

    dd.x = a0 - bb0 - c0 + d0;
    dd.y = a1 - bb1 - c1 + d1;
    dd.z = a2 - bb2 - c2 + d2;
    dd.w = a3 - bb3 - c3 + d3;

    // ---- output stores ----
    const uint32_t b_idx = bc >> 5;        // /32
    const uint32_t ch    = bc & 31u;       // %32
    // out[b][g*32+ch][h][w]; plane = HO*WO = 65536
    const size_t plane = (size_t)HO_ * WO_;
    float* obase = out + ((size_t)b_idx * (4 * C_) + ch) * plane
                       + (size_t)h * WO_ + w4 * 4u;

    *reinterpret_cast<float4*>(obase)                   = pooled;  // group 0
    *reinterpret_cast<float4*>(obase + 1 * C_ * plane)  = dh;      // group 1
    *reinterpret_cast<float4*>(obase + 2 * C_ * plane)  = dv;      // group 2
    *reinterpret_cast<float4*>(obase + 3 * C_ * plane)  = dd;      // group 3
}

extern "C" void kernel_launch(void* const* d_in, const int* in_sizes, int n_in,
                              void* d_out, int out_size)
{
    const float* x = (const float*)d_in[0];
    float* out = (float*)d_out;

    const uint32_t total_threads = B_ * C_ * HO_ * (WO_ / 4);  // 8,388,608
    const uint32_t block = 256;
    const uint32_t grid = total_threads / block;               // 32768

    haar_kernel<<<grid, block>>>(x, out);
}

// round 11
// speedup vs baseline: 1.0004x; 1.0004x over previous
#include <cuda_runtime.h>
#include <cstdint>

// Haar 2x2 wavelet: in (16,32,512,512) f32 -> out (16,128,256,256) f32
// out[b][0*32+c] = pooled, [1*32+c] = diff_h, [2*32+c] = diff_v, [3*32+c] = diff_d
//
// R11: canonical optimum (MLP=4/thread, 32 regs, block 256, default caching)
// with butterfly-factored Haar arithmetic: per 2x2 quad
//   s0=a+b, s1=c+d, g0=a-b, g1=c-d
//   pooled=(s0+s1)*.25, dh=(s0-s1)*.5, dv=(g0+g1)*.5, dd=g0-g1
// (note dv = (a+c)-(b+d) = (a-b)+(c-d) = g0+g1, dd = g0-g1)
// Cuts FADDs ~33% and shortens load->store dep chain by one level.
// Memory config unchanged from the measured optimum; expected neutral
// (fma pipe was 9%, issue 13.6% — memory-bound), serves as final
// convergence check. All other levers measured and rejected (R3/R4/R6/R8).

#define B_  16
#define C_  32
#define H_  512
#define W_  512
#define HO_ 256
#define WO_ 256

__global__ __launch_bounds__(256) void haar_kernel(
    const float* __restrict__ x, float* __restrict__ out)
{
    // One thread = 4 output pixels (float4 wide) at (bc, h, w4*4..w4*4+3)
    // total threads = B*C*HO*(WO/4) = 16*32*256*64 = 8,388,608
    const uint32_t t = blockIdx.x * blockDim.x + threadIdx.x;

    const uint32_t w4  = t & 63u;          // WO/4 = 64
    uint32_t tmp       = t >> 6;
    const uint32_t h   = tmp & 255u;       // HO = 256
    const uint32_t bc  = tmp >> 8;         // 0..511 (b*C + c)

    // ---- input loads: rows 2h and 2h+1, cols 8*w4 .. 8*w4+7 ----
    const float* row0 = x + ((size_t)bc * (H_ * W_)) + (size_t)(2u * h) * W_ + w4 * 8u;
    const float* row1 = row0 + W_;

    const float4 t0 = *reinterpret_cast<const float4*>(row0);
    const float4 t1 = *reinterpret_cast<const float4*>(row0 + 4);
    const float4 b0 = *reinterpret_cast<const float4*>(row1);
    const float4 b1 = *reinterpret_cast<const float4*>(row1 + 4);

    float4 pooled, dh, dv, dd;

    // Butterfly per quad: (a,b) = top pair, (c,d) = bottom pair.
    #define HAARQ(a_, b_, c_, d_, i)                 \
    {                                                \
        const float s0 = (a_) + (b_);                \
        const float s1 = (c_) + (d_);                \
        const float g0 = (a_) - (b_);                \
        const float g1 = (c_) - (d_);                \
        pooled.i = (s0 + s1) * 0.25f;                \
        dh.i     = (s0 - s1) * 0.5f;                 \
        dv.i     = (g0 + g1) * 0.5f;                 \
        dd.i     =  g0 - g1;                         \
    }

    HAARQ(t0.x, t0.y, b0.x, b0.y, x)
    HAARQ(t0.z, t0.w, b0.z, b0.w, y)
    HAARQ(t1.x, t1.y, b1.x, b1.y, z)
    HAARQ(t1.z, t1.w, b1.z, b1.w, w)
    #undef HAARQ

    // ---- output stores ----
    const uint32_t b_idx = bc >> 5;        // /32
    const uint32_t ch    = bc & 31u;       // %32
    // out[b][g*32+ch][h][w]; plane = HO*WO = 65536
    const size_t plane = (size_t)HO_ * WO_;
    float* obase = out + ((size_t)b_idx * (4 * C_) + ch) * plane
                       + (size_t)h * WO_ + w4 * 4u;

    *reinterpret_cast<float4*>(obase)                   = pooled;  // group 0
    *reinterpret_cast<float4*>(obase + 1 * C_ * plane)  = dh;      // group 1
    *reinterpret_cast<float4*>(obase + 2 * C_ * plane)  = dv;      // group 2
    *reinterpret_cast<float4*>(obase + 3 * C_ * plane)  = dd;      // group 3
}

extern "C" void kernel_launch(void* const* d_in, const int* in_sizes, int n_in,
                              void* d_out, int out_size)
{
    const float* x = (const float*)d_in[0];
    float* out = (float*)d_out;

    const uint32_t total_threads = B_ * C_ * HO_ * (WO_ / 4);  // 8,388,608
    const uint32_t block = 256;
    const uint32_t grid = total_threads / block;               // 32768

    haar_kernel<<<grid, block>>>(x, out);
}

// round 12
// speedup vs baseline: 1.0010x; 1.0006x over previous
#include <cuda_runtime.h>
#include <cstdint>

// Haar 2x2 wavelet: in (16,32,512,512) f32 -> out (16,128,256,256) f32
// out[b][0*32+c] = pooled, [1*32+c] = diff_h, [2*32+c] = diff_v, [3*32+c] = diff_d
//
// FINAL — converged (6 reproductions, kernel 149.1-150.8 us, +/-0.5%).
// Streaming kernel at the HBM ceiling: 1.074 GB compulsory traffic in
// ~150 us = 7.1 TB/s SM-side (~89% of 8 TB/s pin spec; ncu DRAM counter
// reads 85-86% because dirty output lines remain in L2 at kernel end).
// All LDG.128/STG.128 fully coalesced, zero over-fetch. L2 = 40% (LTS cap
// not binding), issue = 11.5% (front end idle on memory), fma = 7.4%.
//
// Exhaustively measured search space:
//   - 2x per-thread tile (MLP 4->8): regs 32->48, occ 75->49%, -12%
//   - __ldcs/__stcs evict-first (both or load-only): -1.5..-11%
//   - persistent grid-stride (1184 CTAs): chip MLP falls, -11%
//   - block 512: neutral
//   - butterfly arithmetic (this version): time-neutral, -33% FADDs,
//     regs 31, rel_err 4.5e-8 (reassociation, >>4 orders under threshold)
// Remaining gap to spec is DRAM read/write-turnaround protocol overhead,
// unreachable from SM-side code.

#define B_  16
#define C_  32
#define H_  512
#define W_  512
#define HO_ 256
#define WO_ 256

__global__ __launch_bounds__(256) void haar_kernel(
    const float* __restrict__ x, float* __restrict__ out)
{
    // One thread = 4 output pixels (float4 wide) at (bc, h, w4*4..w4*4+3)
    // total threads = B*C*HO*(WO/4) = 16*32*256*64 = 8,388,608
    const uint32_t t = blockIdx.x * blockDim.x + threadIdx.x;

    const uint32_t w4  = t & 63u;          // WO/4 = 64
    uint32_t tmp       = t >> 6;
    const uint32_t h   = tmp & 255u;       // HO = 256
    const uint32_t bc  = tmp >> 8;         // 0..511 (b*C + c)

    // ---- input loads: rows 2h and 2h+1, cols 8*w4 .. 8*w4+7 ----
    const float* row0 = x + ((size_t)bc * (H_ * W_)) + (size_t)(2u * h) * W_ + w4 * 8u;
    const float* row1 = row0 + W_;

    const float4 t0 = *reinterpret_cast<const float4*>(row0);
    const float4 t1 = *reinterpret_cast<const float4*>(row0 + 4);
    const float4 b0 = *reinterpret_cast<const float4*>(row1);
    const float4 b1 = *reinterpret_cast<const float4*>(row1 + 4);

    float4 pooled, dh, dv, dd;

    // Butterfly per quad: (a,b) = top pair, (c,d) = bottom pair.
    #define HAARQ(a_, b_, c_, d_, i)                 \
    {                                                \
        const float s0 = (a_) + (b_);                \
        const float s1 = (c_) + (d_);                \
        const float g0 = (a_) - (b_);                \
        const float g1 = (c_) - (d_);                \
        pooled.i = (s0 + s1) * 0.25f;                \
        dh.i     = (s0 - s1) * 0.5f;                 \
        dv.i     = (g0 + g1) * 0.5f;                 \
        dd.i     =  g0 - g1;                         \
    }

    HAARQ(t0.x, t0.y, b0.x, b0.y, x)
    HAARQ(t0.z, t0.w, b0.z, b0.w, y)
    HAARQ(t1.x, t1.y, b1.x, b1.y, z)
    HAARQ(t1.z, t1.w, b1.z, b1.w, w)
    #undef HAARQ

    // ---- output stores ----
    const uint32_t b_idx = bc >> 5;        // /32
    const uint32_t ch    = bc & 31u;       // %32
    // out[b][g*32+ch][h][w]; plane = HO*WO = 65536
    const size_t plane = (size_t)HO_ * WO_;
    float* obase = out + ((size_t)b_idx * (4 * C_) + ch) * plane
                       + (size_t)h * WO_ + w4 * 4u;

    *reinterpret_cast<float4*>(obase)                   = pooled;  // group 0
    *reinterpret_cast<float4*>(obase + 1 * C_ * plane)  = dh;      // group 1
    *reinterpret_cast<float4*>(obase + 2 * C_ * plane)  = dv;      // group 2
    *reinterpret_cast<float4*>(obase + 3 * C_ * plane)  = dd;      // group 3
}

extern "C" void kernel_launch(void* const* d_in, const int* in_sizes, int n_in,
                              void* d_out, int out_size)
{
    const float* x = (const float*)d_in[0];
    float* out = (float*)d_out;

    const uint32_t total_threads = B_ * C_ * HO_ * (WO_ / 4);  // 8,388,608
    const uint32_t block = 256;
    const uint32_t grid = total_threads / block;               // 32768

    haar_kernel<<<grid, block>>>(x, out);
}